// round 15
// baseline (speedup 1.0000x reference)
#include <cuda_runtime.h>
#include <cuda_bf16.h>
#include <cstdint>

// PositionwiseMaxPool2D: x [32,128,128,64] f32 NHWC, 2x2/2 pool.
// For each output pixel: pick window position with largest channel-vector
// squared L2 norm, copy its 64 floats to the output.
//
// R13 variant: PERSISTENT single-wave launch. Same per-tile algorithm as the
// 23.8us R7 optimum (4 output pixels per warp, 8 front-batched LDG.E.128 .cs,
// half-warp butterfly + cross-half shfl, branch-free argmax, evict-normal
// stores), but grid = 740 CTAs (148 SMs x 5 CTAs @ 48 regs) with a
// grid-stride loop over the 32768 warp-tiles. Eliminates ~4.5 wave
// transitions: each warp's next-tile loads issue right after its stores
// retire, keeping the LDG stream dense instead of draining per wave.

static constexpr int B  = 32;
static constexpr int H  = 128;
static constexpr int W  = 128;
static constexpr int C  = 64;
static constexpr int OH = 64;
static constexpr int OW = 64;
static constexpr int NOUT = B * OH * OW;            // 131072 output pixels
static constexpr int PIX_PER_WARP = 4;              // OW % 4 == 0
static constexpr int NTILES = NOUT / PIX_PER_WARP;  // 32768 warp-tiles
static constexpr int NBLOCKS = 740;                 // 148 SMs x 5 resident CTAs
static constexpr int NWARPS  = NBLOCKS * 8;         // 5920 warps, ~5.5 tiles each

__global__ __launch_bounds__(256)
void maxpool_pos_kernel(const float* __restrict__ x, float* __restrict__ out) {
    const int warp0 = (blockIdx.x * blockDim.x + threadIdx.x) >> 5;
    const int lane  = threadIdx.x & 31;
    const bool hi   = lane >= 16;

    for (int tile = warp0; tile < NTILES; tile += NWARPS) {
        const int pix0 = tile << 2;               // first of 4 output pixels
        const int ow0  = pix0 & (OW - 1);
        const int oh   = (pix0 >> 6) & (OH - 1);
        const int b    = pix0 >> 12;

        // input rows 2*oh, 2*oh+1 starting at column 2*ow0: 512 floats each
        const size_t base = ((size_t)((b * H + 2 * oh) * W + 2 * ow0)) * C;
        const float4* r0 = reinterpret_cast<const float4*>(x + base);
        const float4* r1 = r0 + (W * C) / 4;      // next input row

        // 8 independent 512B loads -> 8 LDG.E.128 in flight before any use.
        // Chunk q of row r covers window q: candidate (r,j=0) in lanes 0-15,
        // (r,j=1) in lanes 16-31. .cs: touch-once input, evict-first.
        float4 v[8];
        #pragma unroll
        for (int q = 0; q < 4; q++) v[q]     = __ldcs(r0 + q * 32 + lane);
        #pragma unroll
        for (int q = 0; q < 4; q++) v[4 + q] = __ldcs(r1 + q * 32 + lane);

        // Per-lane squared-norm partials; butterfly within each 16-lane half
        // (xor offsets 1,2,4,8 never cross the half boundary).
        float s[8];
        #pragma unroll
        for (int q = 0; q < 8; q++) {
            s[q] = v[q].x * v[q].x + v[q].y * v[q].y
                 + v[q].z * v[q].z + v[q].w * v[q].w;
        }
        #pragma unroll
        for (int off = 8; off; off >>= 1) {
            #pragma unroll
            for (int q = 0; q < 8; q++)
                s[q] += __shfl_xor_sync(0xffffffffu, s[q], off);
        }

        float4* po = reinterpret_cast<float4*>(out + (size_t)pix0 * C);

        #pragma unroll
        for (int w = 0; w < 4; w++) {
            const float sA = s[w];        // (row 0, own column j)
            const float sB = s[4 + w];    // (row 1, own column j)
            const float oA = __shfl_xor_sync(0xffffffffu, sA, 16);
            const float oB = __shfl_xor_sync(0xffffffffu, sB, 16);

            const float n00 = hi ? oA : sA;
            const float n01 = hi ? sA : oA;
            const float n10 = hi ? oB : sB;
            const float n11 = hi ? sB : oB;

            // argmax, first-index tie-break (strict >) to match jnp.argmax
            int   k    = 0;
            float best = n00;
            if (n01 > best) { best = n01; k = 1; }
            if (n10 > best) { best = n10; k = 2; }
            if (n11 > best) { best = n11; k = 3; }

            // lanes of the winning column-half hold the winner's 64 floats.
            // Evict-normal store: output lingers in L2 (writeback absorbed).
            if ((lane >> 4) == (k & 1)) {
                po[w * 16 + (lane & 15)] = (k >> 1) ? v[4 + w] : v[w];
            }
        }
    }
}

extern "C" void kernel_launch(void* const* d_in, const int* in_sizes, int n_in,
                              void* d_out, int out_size) {
    const float* x = (const float*)d_in[0];
    float* out = (float*)d_out;
    maxpool_pos_kernel<<<NBLOCKS, 256>>>(x, out);
}